// round 9
// baseline (speedup 1.0000x reference)
#include <cuda_runtime.h>
#include <cuda_bf16.h>
#include <math.h>
#include <stdint.h>

// Problem constants
#define BATCH    16
#define SEQ      4096
#define CDIM     384
#define MROWS    (BATCH * SEQ)       // 65536
#define QKV_N    (3 * CDIM)          // 1152
#define NHEAD    12
#define HD       32
#define WSZ      8
#define NWIN     64                  // 8x8 windows per image
#define WTOK     64                  // tokens per window

// Scratch (device globals: no allocation allowed)
__device__ float g_qkv[(size_t)MROWS * QKV_N];   // ~302 MB
__device__ float g_att[(size_t)MROWS * CDIM];    // ~100 MB

// ---------------------------------------------------------------------------
// tf32 helpers
// ---------------------------------------------------------------------------
__device__ __forceinline__ void tf32_split(float x, uint32_t& hi, uint32_t& lo)
{
    uint32_t h;
    asm("cvt.rna.tf32.f32 %0, %1;" : "=r"(h) : "f"(x));
    float hf = __uint_as_float(h);
    float l  = x - hf;                       // exact in fp32
    uint32_t lr;
    asm("cvt.rna.tf32.f32 %0, %1;" : "=r"(lr) : "f"(l));
    hi = h; lo = lr;
}

__device__ __forceinline__ void mma_tf32(float c[4],
                                         const uint32_t a[4],
                                         const uint32_t b[2])
{
    asm volatile(
        "mma.sync.aligned.m16n8k8.row.col.f32.tf32.tf32.f32 "
        "{%0,%1,%2,%3}, {%4,%5,%6,%7}, {%8,%9}, {%0,%1,%2,%3};\n"
        : "+f"(c[0]), "+f"(c[1]), "+f"(c[2]), "+f"(c[3])
        : "r"(a[0]), "r"(a[1]), "r"(a[2]), "r"(a[3]),
          "r"(b[0]), "r"(b[1]));
}

// ---------------------------------------------------------------------------
// Split-TF32 GEMM: C[M,N] = A[M,K] @ B[K,N] (+ bias), fp32-accurate via
// Markidis split (hi*hi + hi*lo + lo*hi). BM=BN=128, BK=8, 512 threads,
// 16 warps in 4x4 grid, 32x32 per warp (m16n8k8 tiles), double-buffered smem.
// Requires M%128==0, N%128==0, K%8==0.
// SSTR=136: fragment-load bank = (8*t4 + g) % 32 -> conflict-free.
// ---------------------------------------------------------------------------
#define SSTR 136

template <bool BIAS>
__global__ __launch_bounds__(512, 1)
void gemm_tf32_kernel(const float* __restrict__ A, const float* __restrict__ B,
                      const float* __restrict__ bias, float* __restrict__ C,
                      int M, int N, int K)
{
    __shared__ uint32_t AsH[2][8][SSTR];
    __shared__ uint32_t AsL[2][8][SSTR];
    __shared__ uint32_t BsH[2][8][SSTR];
    __shared__ uint32_t BsL[2][8][SSTR];

    const int tid  = threadIdx.x;
    const int wid  = tid >> 5;
    const int lane = tid & 31;
    const int g    = lane >> 2;     // group id 0..7
    const int t4   = lane & 3;      // thread-in-group 0..3

    const int warpRow = (wid & 3) << 5;    // 0,32,64,96
    const int warpCol = (wid >> 2) << 5;   // 0,32,64,96

    const int rowBase = blockIdx.y * 128;
    const int colBase = blockIdx.x * 128;

    // global load mapping: A tile 128x8 (one float2/thread),
    //                      B tile 8x128 (one float2/thread)
    const int aRow = tid >> 2;            // 0..127
    const int aCol = (tid & 3) << 1;      // 0,2,4,6
    const int bRow = tid >> 6;            // 0..7
    const int bCol = (tid & 63) << 1;     // 0..126

    // incremental prefetch pointers (strength-reduced: no per-iter IMAD chain)
    const float* Ap = A + (size_t)(rowBase + aRow) * K + aCol;
    const float* Bp = B + (size_t)bRow * N + colBase + bCol;
    const size_t bStep = (size_t)8 * N;

    const int nTiles = K >> 3;

    // ---- preload tile 0
    float2 av = *reinterpret_cast<const float2*>(Ap);
    float2 bv = *reinterpret_cast<const float2*>(Bp);
    Ap += 8; Bp += bStep;
    {
        uint32_t h, l;
        tf32_split(av.x, h, l); AsH[0][aCol + 0][aRow] = h; AsL[0][aCol + 0][aRow] = l;
        tf32_split(av.y, h, l); AsH[0][aCol + 1][aRow] = h; AsL[0][aCol + 1][aRow] = l;
        tf32_split(bv.x, h, l); BsH[0][bRow][bCol + 0] = h; BsL[0][bRow][bCol + 0] = l;
        tf32_split(bv.y, h, l); BsH[0][bRow][bCol + 1] = h; BsL[0][bRow][bCol + 1] = l;
    }
    __syncthreads();

    float c[2][4][4];
    #pragma unroll
    for (int mt = 0; mt < 2; mt++)
        #pragma unroll
        for (int nt = 0; nt < 4; nt++)
            #pragma unroll
            for (int r = 0; r < 4; r++) c[mt][nt][r] = 0.f;

    int cur = 0;
    for (int t = 0; t < nTiles; t++) {
        // prefetch next tile's global data (overlaps with compute below)
        if (t + 1 < nTiles) {
            av = *reinterpret_cast<const float2*>(Ap);
            bv = *reinterpret_cast<const float2*>(Bp);
            Ap += 8; Bp += bStep;
        }

        // ---- load fragments from smem (conflict-free: bank = (8*t4+g)%32)
        uint32_t aH[2][4], aL[2][4], bH[4][2], bL[4][2];
        #pragma unroll
        for (int mt = 0; mt < 2; mt++) {
            int m = warpRow + mt * 16 + g;
            aH[mt][0] = AsH[cur][t4    ][m];
            aH[mt][1] = AsH[cur][t4    ][m + 8];
            aH[mt][2] = AsH[cur][t4 + 4][m];
            aH[mt][3] = AsH[cur][t4 + 4][m + 8];
            aL[mt][0] = AsL[cur][t4    ][m];
            aL[mt][1] = AsL[cur][t4    ][m + 8];
            aL[mt][2] = AsL[cur][t4 + 4][m];
            aL[mt][3] = AsL[cur][t4 + 4][m + 8];
        }
        #pragma unroll
        for (int nt = 0; nt < 4; nt++) {
            int n = warpCol + nt * 8 + g;
            bH[nt][0] = BsH[cur][t4    ][n];
            bH[nt][1] = BsH[cur][t4 + 4][n];
            bL[nt][0] = BsL[cur][t4    ][n];
            bL[nt][1] = BsL[cur][t4 + 4][n];
        }

        // ---- 24 HMMA: hi*hi + hi*lo + lo*hi
        #pragma unroll
        for (int mt = 0; mt < 2; mt++)
            #pragma unroll
            for (int nt = 0; nt < 4; nt++) {
                mma_tf32(c[mt][nt], aH[mt], bH[nt]);
                mma_tf32(c[mt][nt], aH[mt], bL[nt]);
                mma_tf32(c[mt][nt], aL[mt], bH[nt]);
            }

        // ---- stage next tile into the other buffer
        if (t + 1 < nTiles) {
            int nxt = cur ^ 1;
            uint32_t h, l;
            tf32_split(av.x, h, l); AsH[nxt][aCol + 0][aRow] = h; AsL[nxt][aCol + 0][aRow] = l;
            tf32_split(av.y, h, l); AsH[nxt][aCol + 1][aRow] = h; AsL[nxt][aCol + 1][aRow] = l;
            tf32_split(bv.x, h, l); BsH[nxt][bRow][bCol + 0] = h; BsL[nxt][bRow][bCol + 0] = l;
            tf32_split(bv.y, h, l); BsH[nxt][bRow][bCol + 1] = h; BsL[nxt][bRow][bCol + 1] = l;
            __syncthreads();
            cur = nxt;
        }
    }

    // ---- epilogue: each thread owns cols (2*t4, 2*t4+1) of rows g / g+8
    #pragma unroll
    for (int mt = 0; mt < 2; mt++) {
        #pragma unroll
        for (int nt = 0; nt < 4; nt++) {
            int col  = colBase + warpCol + nt * 8 + 2 * t4;
            int row0 = rowBase + warpRow + mt * 16 + g;
            int row1 = row0 + 8;
            float2 bb = make_float2(0.f, 0.f);
            if (BIAS) bb = *reinterpret_cast<const float2*>(&bias[col]);
            float2 o0 = make_float2(c[mt][nt][0] + bb.x, c[mt][nt][1] + bb.y);
            float2 o1 = make_float2(c[mt][nt][2] + bb.x, c[mt][nt][3] + bb.y);
            *reinterpret_cast<float2*>(&C[(size_t)row0 * N + col]) = o0;
            *reinterpret_cast<float2*>(&C[(size_t)row1 * N + col]) = o1;
        }
    }
}

// ---------------------------------------------------------------------------
// Window attention: one block per (batch, window, head).
// Gathers q/k/v rows from g_qkv (float4), computes softmax(q k^T * scale) v
// in smem/regs, writes merged-head output into [B,N,C] layout (float4).
// qs/ks padded (stride 33, odd word stride keeps cg-groups on distinct
// banks); vs UNPADDED (stride 32) so P@V reads are LDS.128 broadcasts.
// ---------------------------------------------------------------------------
__global__ __launch_bounds__(256)
void win_attn_kernel(const float* __restrict__ qkv, float* __restrict__ out)
{
    __shared__ float qs[WTOK][HD + 1];
    __shared__ float ks[WTOK][HD + 1];
    __shared__ float vs[WTOK][HD];        // stride 32: aligned for float4
    __shared__ float ps[WTOK][WTOK + 1];

    const int tid = threadIdx.x;
    const int head = blockIdx.x % NHEAD;
    const int bg   = blockIdx.x / NHEAD;
    const int b    = bg / NWIN;
    const int g    = bg % NWIN;
    const int gh   = g >> 3;   // window row
    const int gw   = g & 7;    // window col

    const int qoff = head * HD;
    const int koff = CDIM + head * HD;
    const int voff = 2 * CDIM + head * HD;

    // gather q,k,v with float4 loads: 6 independent LDG.128 per thread
    #pragma unroll
    for (int i = 0; i < 2; i++) {
        int f = tid + i * 256;          // 0..511
        int p = f >> 3;                 // token in window
        int dq = (f & 7) << 2;          // dim (float4 granularity)
        int ph = p >> 3, pw = p & 7;
        int n = ((gh * WSZ + ph) << 6) + gw * WSZ + pw;   // token index (W=64)
        size_t rb = ((size_t)b * SEQ + n) * QKV_N;
        float4 qv = *reinterpret_cast<const float4*>(&qkv[rb + qoff + dq]);
        float4 kv = *reinterpret_cast<const float4*>(&qkv[rb + koff + dq]);
        float4 vv = *reinterpret_cast<const float4*>(&qkv[rb + voff + dq]);
        qs[p][dq + 0] = qv.x; qs[p][dq + 1] = qv.y;
        qs[p][dq + 2] = qv.z; qs[p][dq + 3] = qv.w;
        ks[p][dq + 0] = kv.x; ks[p][dq + 1] = kv.y;
        ks[p][dq + 2] = kv.z; ks[p][dq + 3] = kv.w;
        *reinterpret_cast<float4*>(&vs[p][dq]) = vv;   // aligned: (32p+dq)*4
    }
    __syncthreads();

    const int row = tid >> 2;    // 0..63 : query token
    const int cg  = tid & 3;     // 0..3  : column group
    const int c0  = cg * 16;

    // fold softmax scale into q once (saves a 16-wide multiply pass)
    const float scale = 0.17677669529663687f;  // 1/sqrt(32)
    float qreg[HD];
    #pragma unroll
    for (int d = 0; d < HD; d++) qreg[d] = qs[row][d] * scale;

    float s[16];
    #pragma unroll
    for (int j = 0; j < 16; j++) s[j] = 0.f;
    #pragma unroll
    for (int d = 0; d < HD; d++) {
        float qd = qreg[d];
        #pragma unroll
        for (int j = 0; j < 16; j++)
            s[j] = fmaf(qd, ks[c0 + j][d], s[j]);
    }

    float m = -1e30f;
    #pragma unroll
    for (int j = 0; j < 16; j++) m = fmaxf(m, s[j]);
    m = fmaxf(m, __shfl_xor_sync(0xffffffffu, m, 1));
    m = fmaxf(m, __shfl_xor_sync(0xffffffffu, m, 2));

    float sum = 0.f;
    #pragma unroll
    for (int j = 0; j < 16; j++) { s[j] = __expf(s[j] - m); sum += s[j]; }
    sum += __shfl_xor_sync(0xffffffffu, sum, 1);
    sum += __shfl_xor_sync(0xffffffffu, sum, 2);
    float inv = 1.f / sum;

    #pragma unroll
    for (int j = 0; j < 16; j++) ps[row][c0 + j] = s[j] * inv;
    __syncthreads();

    // O = P @ V : 8 dims per thread; vs reads are 2x LDS.128 broadcast per k
    const int d0 = cg * 8;
    float o[8];
    #pragma unroll
    for (int i = 0; i < 8; i++) o[i] = 0.f;
    #pragma unroll
    for (int k = 0; k < WTOK; k++) {
        float p = ps[row][k];
        float4 v0 = *reinterpret_cast<const float4*>(&vs[k][d0]);
        float4 v1 = *reinterpret_cast<const float4*>(&vs[k][d0 + 4]);
        o[0] = fmaf(p, v0.x, o[0]);
        o[1] = fmaf(p, v0.y, o[1]);
        o[2] = fmaf(p, v0.z, o[2]);
        o[3] = fmaf(p, v0.w, o[3]);
        o[4] = fmaf(p, v1.x, o[4]);
        o[5] = fmaf(p, v1.y, o[5]);
        o[6] = fmaf(p, v1.z, o[6]);
        o[7] = fmaf(p, v1.w, o[7]);
    }

    {
        int ph = row >> 3, pw = row & 7;
        int n = ((gh * WSZ + ph) << 6) + gw * WSZ + pw;
        size_t ob = ((size_t)b * SEQ + n) * CDIM + head * HD + d0;
        float4 w0 = make_float4(o[0], o[1], o[2], o[3]);
        float4 w1 = make_float4(o[4], o[5], o[6], o[7]);
        *reinterpret_cast<float4*>(&out[ob])     = w0;
        *reinterpret_cast<float4*>(&out[ob + 4]) = w1;
    }
}

// ---------------------------------------------------------------------------
extern "C" void kernel_launch(void* const* d_in, const int* in_sizes, int n_in,
                              void* d_out, int out_size)
{
    const float* x      = (const float*)d_in[0];
    const float* qkv_w  = (const float*)d_in[1];
    const float* proj_w = (const float*)d_in[2];
    const float* proj_b = (const float*)d_in[3];
    float* out = (float*)d_out;

    float* qkv_buf = nullptr;
    float* att_buf = nullptr;
    cudaGetSymbolAddress((void**)&qkv_buf, g_qkv);
    cudaGetSymbolAddress((void**)&att_buf, g_att);

    // 1) QKV projection: [65536,384] @ [384,1152] -> g_qkv
    {
        dim3 grid(QKV_N / 128, MROWS / 128);
        gemm_tf32_kernel<false><<<grid, 512>>>(x, qkv_w, nullptr, qkv_buf,
                                               MROWS, QKV_N, CDIM);
    }
    // 2) windowed attention -> g_att in [B,N,C] layout
    {
        int nblk = BATCH * NWIN * NHEAD;   // 12288
        win_attn_kernel<<<nblk, 256>>>(qkv_buf, att_buf);
    }
    // 3) output projection: [65536,384] @ [384,384] + bias -> d_out
    {
        dim3 grid(CDIM / 128, MROWS / 128);
        gemm_tf32_kernel<true><<<grid, 512>>>(att_buf, proj_w, proj_b, out,
                                              MROWS, CDIM, CDIM);
    }
}

// round 10
// speedup vs baseline: 1.2675x; 1.2675x over previous
#include <cuda_runtime.h>
#include <cuda_bf16.h>
#include <math.h>
#include <stdint.h>

// Problem constants
#define BATCH    16
#define SEQ      4096
#define CDIM     384
#define MROWS    (BATCH * SEQ)       // 65536
#define QKV_N    (3 * CDIM)          // 1152
#define NHEAD    12
#define HD       32
#define WSZ      8
#define NWIN     64                  // 8x8 windows per image
#define WTOK     64                  // tokens per window

// Scratch (device globals: no allocation allowed)
__device__ float g_qkv[(size_t)MROWS * QKV_N];   // ~302 MB
__device__ float g_att[(size_t)MROWS * CDIM];    // ~100 MB

// ---------------------------------------------------------------------------
// tf32 helpers
// ---------------------------------------------------------------------------
__device__ __forceinline__ void tf32_split(float x, uint32_t& hi, uint32_t& lo)
{
    uint32_t h;
    asm("cvt.rna.tf32.f32 %0, %1;" : "=r"(h) : "f"(x));
    float hf = __uint_as_float(h);
    float l  = x - hf;                       // exact in fp32
    uint32_t lr;
    asm("cvt.rna.tf32.f32 %0, %1;" : "=r"(lr) : "f"(l));
    hi = h; lo = lr;
}

__device__ __forceinline__ void mma_tf32(float c[4],
                                         const uint32_t a[4],
                                         const uint32_t b[2])
{
    asm volatile(
        "mma.sync.aligned.m16n8k8.row.col.f32.tf32.tf32.f32 "
        "{%0,%1,%2,%3}, {%4,%5,%6,%7}, {%8,%9}, {%0,%1,%2,%3};\n"
        : "+f"(c[0]), "+f"(c[1]), "+f"(c[2]), "+f"(c[3])
        : "r"(a[0]), "r"(a[1]), "r"(a[2]), "r"(a[3]),
          "r"(b[0]), "r"(b[1]));
}

// ---------------------------------------------------------------------------
// Split-TF32 GEMM: C[M,N] = A[M,K] @ B[K,N] (+ bias), fp32-accurate via
// Markidis split (hi*hi + hi*lo + lo*hi).
// BM=64, BN=128, BK=8, 256 threads (8 warps, 2x4 grid of 32x32 warp tiles),
// double-buffered RAW-float smem (split happens after fragment load),
// __launch_bounds__(256,2) -> 2 CTAs/SM for barrier overlap.
// Requires M%64==0, N%128==0, K%8==0.
// ASTR=72 / BSTR=136: fragment bank = (8*k + idx) % 32 -> conflict-free.
// ---------------------------------------------------------------------------
#define ASTR 72
#define BSTR 136

template <bool BIAS>
__global__ __launch_bounds__(256, 2)
void gemm_tf32_kernel(const float* __restrict__ A, const float* __restrict__ B,
                      const float* __restrict__ bias, float* __restrict__ C,
                      int M, int N, int K)
{
    __shared__ __align__(16) float As[2][8][ASTR];   // raw floats
    __shared__ __align__(16) float Bs[2][8][BSTR];

    const int tid  = threadIdx.x;
    const int wid  = tid >> 5;
    const int lane = tid & 31;
    const int g    = lane >> 2;     // 0..7
    const int t4   = lane & 3;      // 0..3

    const int warpRow = (wid & 1) << 5;    // 0,32
    const int warpCol = (wid >> 1) << 5;   // 0,32,64,96

    const int rowBase = blockIdx.y * 64;
    const int colBase = blockIdx.x * 128;

    // global load mapping: A tile 64x8 (one float2/thread),
    //                      B tile 8x128 (one float4/thread)
    const int aRow = tid >> 2;            // 0..63
    const int aCol = (tid & 3) << 1;      // 0,2,4,6
    const int bRow = tid >> 5;            // 0..7
    const int bCol = (tid & 31) << 2;     // 0..124

    const float* Ap = A + (size_t)(rowBase + aRow) * K + aCol;
    const float* Bp = B + (size_t)bRow * N + colBase + bCol;
    const size_t bStep = (size_t)8 * N;

    const int nTiles = K >> 3;

    // ---- preload tile 0 (raw floats, no split at store)
    float2 av = *reinterpret_cast<const float2*>(Ap);
    float4 bv = *reinterpret_cast<const float4*>(Bp);
    Ap += 8; Bp += bStep;
    As[0][aCol + 0][aRow] = av.x;
    As[0][aCol + 1][aRow] = av.y;
    *reinterpret_cast<float4*>(&Bs[0][bRow][bCol]) = bv;
    __syncthreads();

    float c[2][4][4];
    #pragma unroll
    for (int mt = 0; mt < 2; mt++)
        #pragma unroll
        for (int nt = 0; nt < 4; nt++)
            #pragma unroll
            for (int r = 0; r < 4; r++) c[mt][nt][r] = 0.f;

    int cur = 0;
    for (int t = 0; t < nTiles; t++) {
        // prefetch next tile's global data (overlaps with compute below)
        if (t + 1 < nTiles) {
            av = *reinterpret_cast<const float2*>(Ap);
            bv = *reinterpret_cast<const float4*>(Bp);
            Ap += 8; Bp += bStep;
        }

        // ---- load RAW fragments from smem, split into hi/lo in registers
        uint32_t aH[2][4], aL[2][4], bH[4][2], bL[4][2];
        #pragma unroll
        for (int mt = 0; mt < 2; mt++) {
            int m = warpRow + mt * 16 + g;
            float r0 = As[cur][t4    ][m];
            float r1 = As[cur][t4    ][m + 8];
            float r2 = As[cur][t4 + 4][m];
            float r3 = As[cur][t4 + 4][m + 8];
            tf32_split(r0, aH[mt][0], aL[mt][0]);
            tf32_split(r1, aH[mt][1], aL[mt][1]);
            tf32_split(r2, aH[mt][2], aL[mt][2]);
            tf32_split(r3, aH[mt][3], aL[mt][3]);
        }
        #pragma unroll
        for (int nt = 0; nt < 4; nt++) {
            int n = warpCol + nt * 8 + g;
            float r0 = Bs[cur][t4    ][n];
            float r1 = Bs[cur][t4 + 4][n];
            tf32_split(r0, bH[nt][0], bL[nt][0]);
            tf32_split(r1, bH[nt][1], bL[nt][1]);
        }

        // ---- 24 HMMA: hi*hi + hi*lo + lo*hi
        #pragma unroll
        for (int mt = 0; mt < 2; mt++)
            #pragma unroll
            for (int nt = 0; nt < 4; nt++) {
                mma_tf32(c[mt][nt], aH[mt], bH[nt]);
                mma_tf32(c[mt][nt], aH[mt], bL[nt]);
                mma_tf32(c[mt][nt], aL[mt], bH[nt]);
            }

        // ---- stage next tile (raw) into the other buffer
        if (t + 1 < nTiles) {
            int nxt = cur ^ 1;
            As[nxt][aCol + 0][aRow] = av.x;
            As[nxt][aCol + 1][aRow] = av.y;
            *reinterpret_cast<float4*>(&Bs[nxt][bRow][bCol]) = bv;
            __syncthreads();
            cur = nxt;
        }
    }

    // ---- epilogue: each thread owns cols (2*t4, 2*t4+1) of rows g / g+8
    #pragma unroll
    for (int mt = 0; mt < 2; mt++) {
        #pragma unroll
        for (int nt = 0; nt < 4; nt++) {
            int col  = colBase + warpCol + nt * 8 + 2 * t4;
            int row0 = rowBase + warpRow + mt * 16 + g;
            int row1 = row0 + 8;
            float2 bb = make_float2(0.f, 0.f);
            if (BIAS) bb = *reinterpret_cast<const float2*>(&bias[col]);
            float2 o0 = make_float2(c[mt][nt][0] + bb.x, c[mt][nt][1] + bb.y);
            float2 o1 = make_float2(c[mt][nt][2] + bb.x, c[mt][nt][3] + bb.y);
            *reinterpret_cast<float2*>(&C[(size_t)row0 * N + col]) = o0;
            *reinterpret_cast<float2*>(&C[(size_t)row1 * N + col]) = o1;
        }
    }
}

// ---------------------------------------------------------------------------
// Window attention: one block per (batch, window, head), 256 threads.
// Per-thread work: 2 query rows x 8 score cols (cols strided by 8 so the
// per-(d,jj) k-row reads hit 8 distinct banks: bank=(cg8+8jj+d)%32).
// P@V: 2 rows x 4 output dims, float4 broadcast v reads.
// ---------------------------------------------------------------------------
__global__ __launch_bounds__(256)
void win_attn_kernel(const float* __restrict__ qkv, float* __restrict__ out)
{
    __shared__ float qs[WTOK][HD + 1];
    __shared__ float ks[WTOK][HD + 1];
    __shared__ float vs[WTOK][HD];        // stride 32: aligned for float4
    __shared__ float ps[WTOK][WTOK + 1];

    const int tid = threadIdx.x;
    const int head = blockIdx.x % NHEAD;
    const int bg   = blockIdx.x / NHEAD;
    const int b    = bg / NWIN;
    const int g    = bg % NWIN;
    const int gh   = g >> 3;   // window row
    const int gw   = g & 7;    // window col

    const int qoff = head * HD;
    const int koff = CDIM + head * HD;
    const int voff = 2 * CDIM + head * HD;

    // gather q,k,v with float4 loads: 6 independent LDG.128 per thread
    #pragma unroll
    for (int i = 0; i < 2; i++) {
        int f = tid + i * 256;          // 0..511
        int p = f >> 3;                 // token in window
        int dq = (f & 7) << 2;          // dim (float4 granularity)
        int ph = p >> 3, pw = p & 7;
        int n = ((gh * WSZ + ph) << 6) + gw * WSZ + pw;   // token index (W=64)
        size_t rb = ((size_t)b * SEQ + n) * QKV_N;
        float4 qv = *reinterpret_cast<const float4*>(&qkv[rb + qoff + dq]);
        float4 kv = *reinterpret_cast<const float4*>(&qkv[rb + koff + dq]);
        float4 vv = *reinterpret_cast<const float4*>(&qkv[rb + voff + dq]);
        qs[p][dq + 0] = qv.x; qs[p][dq + 1] = qv.y;
        qs[p][dq + 2] = qv.z; qs[p][dq + 3] = qv.w;
        ks[p][dq + 0] = kv.x; ks[p][dq + 1] = kv.y;
        ks[p][dq + 2] = kv.z; ks[p][dq + 3] = kv.w;
        *reinterpret_cast<float4*>(&vs[p][dq]) = vv;   // aligned: (32p+dq)*4
    }
    __syncthreads();

    const int wid  = tid >> 5;
    const int lane = tid & 31;
    const int cg8  = lane & 7;     // column-group: cols cg8, cg8+8, ..., cg8+56
    const int rs   = lane >> 3;    // row-select 0..3
    const int r0   = wid * 8 + rs; // query row A
    const int r1   = r0 + 4;       // query row B

    // S = q k^T for 2 rows x 8 strided cols per thread
    float s0[8], s1[8];
    #pragma unroll
    for (int j = 0; j < 8; j++) { s0[j] = 0.f; s1[j] = 0.f; }
    #pragma unroll
    for (int d = 0; d < HD; d++) {
        float q0 = qs[r0][d];
        float q1 = qs[r1][d];
        #pragma unroll
        for (int jj = 0; jj < 8; jj++) {
            float kv = ks[cg8 + 8 * jj][d];   // conflict-free: bank cg8-distinct
            s0[jj] = fmaf(q0, kv, s0[jj]);
            s1[jj] = fmaf(q1, kv, s1[jj]);
        }
    }

    const float scale = 0.17677669529663687f;  // 1/sqrt(32)
    float m0 = -1e30f, m1 = -1e30f;
    #pragma unroll
    for (int jj = 0; jj < 8; jj++) {
        s0[jj] *= scale; s1[jj] *= scale;
        m0 = fmaxf(m0, s0[jj]); m1 = fmaxf(m1, s1[jj]);
    }
    // reduce across the 8 column-groups (xor over cg8 bits 0..2)
    #pragma unroll
    for (int sh = 1; sh <= 4; sh <<= 1) {
        m0 = fmaxf(m0, __shfl_xor_sync(0xffffffffu, m0, sh));
        m1 = fmaxf(m1, __shfl_xor_sync(0xffffffffu, m1, sh));
    }

    float sum0 = 0.f, sum1 = 0.f;
    #pragma unroll
    for (int jj = 0; jj < 8; jj++) {
        s0[jj] = __expf(s0[jj] - m0); sum0 += s0[jj];
        s1[jj] = __expf(s1[jj] - m1); sum1 += s1[jj];
    }
    #pragma unroll
    for (int sh = 1; sh <= 4; sh <<= 1) {
        sum0 += __shfl_xor_sync(0xffffffffu, sum0, sh);
        sum1 += __shfl_xor_sync(0xffffffffu, sum1, sh);
    }
    float inv0 = 1.f / sum0, inv1 = 1.f / sum1;

    #pragma unroll
    for (int jj = 0; jj < 8; jj++) {
        ps[r0][cg8 + 8 * jj] = s0[jj] * inv0;
        ps[r1][cg8 + 8 * jj] = s1[jj] * inv1;
    }
    __syncthreads();

    // O = P @ V : 2 rows x 4 dims per thread; v reads are float4 broadcast
    const int d0 = cg8 * 4;
    float o0[4] = {0.f, 0.f, 0.f, 0.f};
    float o1[4] = {0.f, 0.f, 0.f, 0.f};
    #pragma unroll
    for (int k = 0; k < WTOK; k++) {
        float p0 = ps[r0][k];
        float p1 = ps[r1][k];
        float4 v = *reinterpret_cast<const float4*>(&vs[k][d0]);
        o0[0] = fmaf(p0, v.x, o0[0]); o0[1] = fmaf(p0, v.y, o0[1]);
        o0[2] = fmaf(p0, v.z, o0[2]); o0[3] = fmaf(p0, v.w, o0[3]);
        o1[0] = fmaf(p1, v.x, o1[0]); o1[1] = fmaf(p1, v.y, o1[1]);
        o1[2] = fmaf(p1, v.z, o1[2]); o1[3] = fmaf(p1, v.w, o1[3]);
    }

    // write to [B, N, C] with head-merge + window reverse (16B aligned)
    {
        int ph0 = r0 >> 3, pw0 = r0 & 7;
        int n0 = ((gh * WSZ + ph0) << 6) + gw * WSZ + pw0;
        size_t ob0 = ((size_t)b * SEQ + n0) * CDIM + head * HD + d0;
        *reinterpret_cast<float4*>(&out[ob0]) = make_float4(o0[0], o0[1], o0[2], o0[3]);

        int ph1 = r1 >> 3, pw1 = r1 & 7;
        int n1 = ((gh * WSZ + ph1) << 6) + gw * WSZ + pw1;
        size_t ob1 = ((size_t)b * SEQ + n1) * CDIM + head * HD + d0;
        *reinterpret_cast<float4*>(&out[ob1]) = make_float4(o1[0], o1[1], o1[2], o1[3]);
    }
}

// ---------------------------------------------------------------------------
extern "C" void kernel_launch(void* const* d_in, const int* in_sizes, int n_in,
                              void* d_out, int out_size)
{
    const float* x      = (const float*)d_in[0];
    const float* qkv_w  = (const float*)d_in[1];
    const float* proj_w = (const float*)d_in[2];
    const float* proj_b = (const float*)d_in[3];
    float* out = (float*)d_out;

    float* qkv_buf = nullptr;
    float* att_buf = nullptr;
    cudaGetSymbolAddress((void**)&qkv_buf, g_qkv);
    cudaGetSymbolAddress((void**)&att_buf, g_att);

    // 1) QKV projection: [65536,384] @ [384,1152] -> g_qkv
    {
        dim3 grid(QKV_N / 128, MROWS / 64);
        gemm_tf32_kernel<false><<<grid, 256>>>(x, qkv_w, nullptr, qkv_buf,
                                               MROWS, QKV_N, CDIM);
    }
    // 2) windowed attention -> g_att in [B,N,C] layout
    {
        int nblk = BATCH * NWIN * NHEAD;   // 12288
        win_attn_kernel<<<nblk, 256>>>(qkv_buf, att_buf);
    }
    // 3) output projection: [65536,384] @ [384,384] + bias -> d_out
    {
        dim3 grid(CDIM / 128, MROWS / 64);
        gemm_tf32_kernel<true><<<grid, 256>>>(att_buf, proj_w, proj_b, out,
                                              MROWS, CDIM, CDIM);
    }
}